// round 9
// baseline (speedup 1.0000x reference)
#include <cuda_runtime.h>
#include <math_constants.h>

#define B 8
#define T 200
#define U 50
#define V 1024

#define NCOL   99          // 50 blank cols + 49 emit cols
#define TP     320         // padded column stride
#define FRONT  52          // front padding (-inf)
#define DUMMY  99          // all -inf column
#define NCOLS  100

#define LOG2E 1.4426950408889634f
#define LN2   0.6931471805599453f
#define NEGINF (-CUDART_INF_F)

__device__ float    g_scratch[B * NCOL * T];   // normalized log2-probs, [b][col][t]
__device__ float    g_partial[B];
__device__ unsigned g_count;

// base-2 logaddexp, NaN-free: la2(-inf,-inf) = -inf (clamp maps NaN diff -> -130)
__device__ __forceinline__ float la2(float a, float b) {
    float m = fmaxf(a, b);
    float d = a - b;                          // NaN iff both -inf
    float c = fmaxf(-fabsf(d), -130.0f);      // NaN -> -130 -> 2^-130 ~ 0
    float e;
    asm("ex2.approx.ftz.f32 %0, %1;" : "=f"(e) : "f"(c));
    float l;
    asm("lg2.approx.ftz.f32 %0, %1;" : "=f"(l) : "f"(1.0f + e));
    return m + l;
}

// ---------------------------------------------------------------------------
// Kernel A: 4 warps/block, one (batch, column) per warp. Gather strided h
// column, logsumexp over T (softmax axis is T!), store log2-scaled values.
// Also resets the cross-block arrival counter for this replay.
// ---------------------------------------------------------------------------
__global__ __launch_bounds__(128) void rnnt_gather_kernel(
    const float* __restrict__ h,
    const int*   __restrict__ targets)   // (B, U-1)
{
    if (blockIdx.x == 0 && threadIdx.x == 0) g_count = 0;

    const int gwarp = blockIdx.x * 4 + (threadIdx.x >> 5);   // 792 warps exactly
    const int lane  = threadIdx.x & 31;
    const int b     = gwarp / NCOL;
    const int c     = gwarp - b * NCOL;

    int u, v;
    if (c < U) { u = c;     v = 0; }
    else       { u = c - U; v = targets[b * (U - 1) + u]; }

    const float* col = h + (size_t)b * T * U * V + (size_t)u * V + v;
    const size_t tstride = (size_t)U * V;

    float x[7];
    #pragma unroll
    for (int k = 0; k < 7; k++) {
        int t = lane + 32 * k;
        x[k] = (t < T) ? col[(size_t)t * tstride] : NEGINF;
    }
    float m = x[0];
    #pragma unroll
    for (int k = 1; k < 7; k++) m = fmaxf(m, x[k]);
    #pragma unroll
    for (int o = 16; o > 0; o >>= 1) m = fmaxf(m, __shfl_xor_sync(0xffffffff, m, o));
    float s = 0.0f;
    #pragma unroll
    for (int k = 0; k < 7; k++) s += __expf(x[k] - m);
    #pragma unroll
    for (int o = 16; o > 0; o >>= 1) s += __shfl_xor_sync(0xffffffff, s, o);
    const float lse = m + __logf(s);

    float* dst = g_scratch + (size_t)(b * NCOL + c) * T;
    #pragma unroll
    for (int k = 0; k < 7; k++) {
        int t = lane + 32 * k;
        if (t < T) dst[t] = (x[k] - lse) * LOG2E;
    }
}

// ---------------------------------------------------------------------------
// Kernel B: one block per batch. Stage -inf-padded columns in smem, warp 0
// runs the wavefront DP. Each lane computes 3 columns: uR=2l-1 (redundant
// duplicate of lane l-1's u1 -- bitwise identical recurrence), u0=2l, u1=2l+1.
// The shfl feeds only the redundant column, whose value is consumed one
// diagonal later, taking the 26-cycle shfl off the per-diagonal chain.
// Last block to finish reduces the batch mean (deterministic fixed order).
// ---------------------------------------------------------------------------
__global__ __launch_bounds__(512, 1) void rnnt_dp_kernel(
    const int* __restrict__ input_lens,
    const int* __restrict__ target_lens,
    float* __restrict__ out)
{
    extern __shared__ float smem[];
    const int b   = blockIdx.x;
    const int tid = threadIdx.x;

    // 1) flood -inf (padding + dummy column), vectorized
    {
        float4* s4 = reinterpret_cast<float4*>(smem);
        const float4 ninf4 = make_float4(NEGINF, NEGINF, NEGINF, NEGINF);
        for (int i = tid; i < NCOLS * TP / 4; i += 512) s4[i] = ninf4;
    }
    __syncthreads();

    // 2) fill valid region from scratch (L2-resident)
    //    blank col u:  smem[u*TP      + FRONT + t + 1] = blank[t][u]
    //    emit  col u:  smem[(U+u)*TP  + FRONT + t]     = emit[t][u]
    const float* src = g_scratch + (size_t)b * NCOL * T;
    for (int i = tid; i < NCOL * T; i += 512) {
        int col = i / T;
        int t   = i - col * T;
        smem[col * TP + FRONT + t + (col < U ? 1 : 0)] = src[i];
    }
    __syncthreads();
    if (tid >= 32) return;

    const int lane = tid;
    const int ti = input_lens[b]  - 1;
    const int ui = target_lens[b] - 1;

    const int uR = 2 * lane - 1;
    const int u0 = 2 * lane;
    const int u1 = u0 + 1;

    // pointer per (column, arm): base + FRONT, indexed by diagonal d
    //   blank arm of col u reads smem[u*TP + FRONT + (d - u)]
    //   emit  arm of col u reads smem[(U+u-1)*TP + FRONT + (d - u)]
    const float* BR = smem + ((uR >= 1 && uR < U) ? uR * TP - uR           : DUMMY * TP) + FRONT;
    const float* ER = smem + ((uR >= 1 && uR < U) ? (U + uR - 1) * TP - uR : DUMMY * TP) + FRONT;
    const float* B0 = smem + ((u0 < U)            ? u0 * TP - u0           : DUMMY * TP) + FRONT;
    const float* E0 = smem + ((u0 >= 1 && u0 < U) ? (U + u0 - 1) * TP - u0 : DUMMY * TP) + FRONT;
    const float* B1 = smem + ((u1 < U)            ? u1 * TP - u1           : DUMMY * TP) + FRONT;
    const float* E1 = smem + ((u1 < U)            ? (U + u0) * TP - u1     : DUMMY * TP) + FRONT;

    float pR = NEGINF;
    float p0 = (lane == 0) ? 0.0f : NEGINF;     // alpha[0][0] = 0
    float p1 = NEGINF;
    const int dmax = ti + ui;

    float bR = BR[1], eR = ER[1], b0 = B0[1], e0 = E0[1], b1 = B1[1], e1 = E1[1];
    for (int d = 1; d <= dmax; d++) {
        // prefetch next diagonal under this diagonal's math
        float nbR = BR[d + 1], neR = ER[d + 1];
        float nb0 = B0[d + 1], ne0 = E0[d + 1];
        float nb1 = B1[d + 1], ne1 = E1[d + 1];

        float s0 = __shfl_up_sync(0xffffffff, p0, 1);   // lane l-1's col 2l-2 (diag d-1)

        float nR = la2(pR + bR, s0 + eR);   // col 2l-1 (redundant)
        float n0 = la2(p0 + b0, pR + e0);   // col 2l   (emit arm = own redundant col!)
        float n1 = la2(p1 + b1, p0 + e1);   // col 2l+1

        pR = nR; p0 = n0; p1 = n1;
        bR = nbR; eR = neR; b0 = nb0; e0 = ne0; b1 = nb1; e1 = ne1;
    }

    // cell (ti,ui) lands on diagonal dmax in lane ui>>1
    if (lane == (ui >> 1)) {
        float res  = (ui & 1) ? p1 : p0;
        float bfin = smem[ui * TP + FRONT + ti + 1];    // blank[ti][ui] (log2)
        g_partial[b] = -(res + bfin) * LN2;
    }
    __syncwarp();

    // last-block deterministic reduction (counter reset by gather kernel)
    if (lane == 0) {
        __threadfence();
        if (atomicAdd(&g_count, 1u) == B - 1) {
            __threadfence();
            const volatile float* gp = g_partial;
            float s = 0.0f;
            #pragma unroll
            for (int i = 0; i < B; i++) s += gp[i];
            out[0] = s * (1.0f / B);
        }
    }
}

extern "C" void kernel_launch(void* const* d_in, const int* in_sizes, int n_in,
                              void* d_out, int out_size) {
    const float* h           = (const float*)d_in[0];
    const int*   targets     = (const int*)d_in[1];
    const int*   input_lens  = (const int*)d_in[2];
    const int*   target_lens = (const int*)d_in[3];
    float*       out         = (float*)d_out;

    const size_t smem_bytes = (size_t)NCOLS * TP * sizeof(float);   // 128000 B
    static int smem_set = 0;
    if (!smem_set) {
        cudaFuncSetAttribute(rnnt_dp_kernel,
                             cudaFuncAttributeMaxDynamicSharedMemorySize,
                             (int)smem_bytes);
        smem_set = 1;
    }

    rnnt_gather_kernel<<<(B * NCOL) / 4, 128>>>(h, targets);
    rnnt_dp_kernel<<<B, 512, smem_bytes>>>(input_lens, target_lens, out);
}

// round 11
// speedup vs baseline: 1.2154x; 1.2154x over previous
#include <cuda_runtime.h>
#include <math_constants.h>

#define B 8
#define T 200
#define U 50
#define V 1024

#define NCOL   99          // 50 blank cols + 49 emit cols
#define TP     320         // padded column stride (words)
#define FRONT  52          // front padding
#define DUMMY  99          // all-dead column
#define NCOLS  100

#define LOG2E 1.4426950408889634f
#define LN2   0.6931471805599453f
#define DEAD  (-1.0e30f)

__device__ float    g_scratch[B * NCOL * T];   // normalized log2-probs, [b][col][t]
__device__ float    g_partial[B];
__device__ unsigned g_count;

// base-2 logaddexp on finite "dead = -1e30" domain (never produces NaN):
//   la2(a,b) = max(a,b) + lg2(1 + 2^(-|a-b|))
__device__ __forceinline__ float la2(float a, float b) {
    float m = fmaxf(a, b);
    float d = a - b;                 // finite always (dead-dead = 0)
    float c = fminf(d, -d);          // -|d|  (one FMNMX, neg modifier free)
    float e;
    asm("ex2.approx.ftz.f32 %0, %1;" : "=f"(e) : "f"(c));
    float l;
    asm("lg2.approx.ftz.f32 %0, %1;" : "=f"(l) : "f"(1.0f + e));
    return m + l;
}

// ---------------------------------------------------------------------------
// Kernel A: 4 warps/block, one (batch, column) per warp. Gather strided h
// column, logsumexp over T (softmax axis is T!), store log2-scaled values.
// Also resets the cross-block arrival counter for this graph replay.
// ---------------------------------------------------------------------------
__global__ __launch_bounds__(128) void rnnt_gather_kernel(
    const float* __restrict__ h,
    const int*   __restrict__ targets)   // (B, U-1)
{
    if (blockIdx.x == 0 && threadIdx.x == 0) g_count = 0;

    const int gwarp = blockIdx.x * 4 + (threadIdx.x >> 5);   // 792 warps exactly
    const int lane  = threadIdx.x & 31;
    const int b     = gwarp / NCOL;
    const int c     = gwarp - b * NCOL;

    int u, v;
    if (c < U) { u = c;     v = 0; }
    else       { u = c - U; v = targets[b * (U - 1) + u]; }

    const float* col = h + (size_t)b * T * U * V + (size_t)u * V + v;
    const size_t tstride = (size_t)U * V;

    float x[7];
    #pragma unroll
    for (int k = 0; k < 7; k++) {
        int t = lane + 32 * k;
        x[k] = (t < T) ? col[(size_t)t * tstride] : -CUDART_INF_F;
    }
    float m = x[0];
    #pragma unroll
    for (int k = 1; k < 7; k++) m = fmaxf(m, x[k]);
    #pragma unroll
    for (int o = 16; o > 0; o >>= 1) m = fmaxf(m, __shfl_xor_sync(0xffffffff, m, o));
    float s = 0.0f;
    #pragma unroll
    for (int k = 0; k < 7; k++) s += __expf(x[k] - m);
    #pragma unroll
    for (int o = 16; o > 0; o >>= 1) s += __shfl_xor_sync(0xffffffff, s, o);
    const float lse = m + __logf(s);

    float* dst = g_scratch + (size_t)(b * NCOL + c) * T;
    #pragma unroll
    for (int k = 0; k < 7; k++) {
        int t = lane + 32 * k;
        if (t < T) dst[t] = (x[k] - lse) * LOG2E;
    }
}

// ---------------------------------------------------------------------------
// Kernel B: one block per batch. Stage dead-padded columns in smem, then
// meet-in-the-middle: warp 0 runs the FORWARD alpha wavefront to diagonal
// D = dmax/2 while warp 1 concurrently runs the BACKWARD beta wavefront from
// dmax down to D (different SMSPs -> independent MUFU/issue pipes). Combine:
//   loss = logsumexp_u(alpha_D[u] + beta_D[u])   (exact path partition at D)
// Both wavefronts use the redundant-column trick so the shfl feeds only a
// duplicated column consumed one diagonal later.
// Layout: blank[t][u] at smem[u*TP + FRONT + t + 1]
//         emit [t][u] at smem[(U+u)*TP + FRONT + t]
// Last block to finish reduces the batch mean (deterministic fixed order).
// ---------------------------------------------------------------------------
__global__ __launch_bounds__(512, 1) void rnnt_dp_kernel(
    const int* __restrict__ input_lens,
    const int* __restrict__ target_lens,
    float* __restrict__ out)
{
    extern __shared__ float smem[];
    float* abuf = smem + NCOLS * TP;        // 64 floats: alpha on diag D
    float* bbuf = abuf + 64;                // 64 floats: beta  on diag D

    const int b   = blockIdx.x;
    const int tid = threadIdx.x;

    // 1) flood dead (padding + dummy column), vectorized
    {
        float4* s4 = reinterpret_cast<float4*>(smem);
        const float4 dead4 = make_float4(DEAD, DEAD, DEAD, DEAD);
        for (int i = tid; i < NCOLS * TP / 4; i += 512) s4[i] = dead4;
    }
    __syncthreads();

    // 2) fill valid region from scratch (L2-resident)
    const float* src = g_scratch + (size_t)b * NCOL * T;
    for (int i = tid; i < NCOL * T; i += 512) {
        int col = i / T;
        int t   = i - col * T;
        smem[col * TP + FRONT + t + (col < U ? 1 : 0)] = src[i];
    }
    __syncthreads();

    const int lane = tid & 31;
    const int wid  = tid >> 5;
    const int ti   = input_lens[b]  - 1;
    const int ui   = target_lens[b] - 1;
    const int dmax = ti + ui;
    const int D    = dmax >> 1;

    if (wid == 0) {
        // ---------- forward alpha: diagonals 1..D ----------
        // lane computes cols uR=2l-1 (redundant copy of left neighbor's u1),
        // u0=2l, u1=2l+1.  Cell (t,u), t=d-u:
        //   blank arm reads smem[u*TP + FRONT + (d-u)]            = blank[t-1][u]
        //   emit  arm reads smem[(U+u-1)*TP + FRONT + (d-u)]      = emit[t][u-1]
        const int uR = 2 * lane - 1;
        const int u0 = 2 * lane;
        const int u1 = u0 + 1;

        const float* BR = smem + ((uR >= 1 && uR < U) ? uR * TP - uR           : DUMMY * TP) + FRONT;
        const float* ER = smem + ((uR >= 1 && uR < U) ? (U + uR - 1) * TP - uR : DUMMY * TP) + FRONT;
        const float* B0 = smem + ((u0 < U)            ? u0 * TP - u0           : DUMMY * TP) + FRONT;
        const float* E0 = smem + ((u0 >= 1 && u0 < U) ? (U + u0 - 1) * TP - u0 : DUMMY * TP) + FRONT;
        const float* B1 = smem + ((u1 < U)            ? u1 * TP - u1           : DUMMY * TP) + FRONT;
        const float* E1 = smem + ((u1 < U)            ? (U + u0) * TP - u1     : DUMMY * TP) + FRONT;

        float pR = DEAD;
        float p0 = (lane == 0) ? 0.0f : DEAD;   // alpha[0][0] = 0
        float p1 = DEAD;

        float bR = BR[1], eR = ER[1], b0 = B0[1], e0 = E0[1], b1 = B1[1], e1 = E1[1];
        #pragma unroll 2
        for (int d = 1; d <= D; d++) {
            float nbR = BR[d + 1], neR = ER[d + 1];
            float nb0 = B0[d + 1], ne0 = E0[d + 1];
            float nb1 = B1[d + 1], ne1 = E1[d + 1];

            float s0 = __shfl_up_sync(0xffffffff, p0, 1);   // lane l-1's col 2l-2

            float nR = la2(pR + bR, s0 + eR);   // col 2l-1 (redundant)
            float n0 = la2(p0 + b0, pR + e0);   // col 2l
            float n1 = la2(p1 + b1, p0 + e1);   // col 2l+1

            pR = nR; p0 = n0; p1 = n1;
            bR = nbR; eR = neR; b0 = nb0; e0 = ne0; b1 = nb1; e1 = ne1;
        }
        if (u0 < 64) abuf[u0] = p0;
        if (u1 < 64) abuf[u1] = p1;
    } else if (wid == 1) {
        // ---------- backward beta: diagonals dmax-1 .. D ----------
        // beta[t][u] = la2(beta[t+1][u] + blank[t][u], beta[t][u+1] + emit[t][u])
        // lane computes cols u0=2l, u1=2l+1, redundant uR2=2l+2 (copy of right
        // neighbor's u0).  Cell (t,u), t=d-u:
        //   blank arm reads smem[u*TP + FRONT + (d-u) + 1]   = blank[t][u]
        //   emit  arm reads smem[(U+u)*TP + FRONT + (d-u)]   = emit[t][u]
        const int u0  = 2 * lane;
        const int u1  = u0 + 1;
        const int uR2 = u0 + 2;

        const float* B0b = smem + ((u0 < U)      ? u0 * TP - u0        : DUMMY * TP) + FRONT + 1;
        const float* E0b = smem + ((u0 < U - 1)  ? (U + u0) * TP - u0  : DUMMY * TP) + FRONT;
        const float* B1b = smem + ((u1 < U)      ? u1 * TP - u1        : DUMMY * TP) + FRONT + 1;
        const float* E1b = smem + ((u1 < U - 1)  ? (U + u1) * TP - u1  : DUMMY * TP) + FRONT;
        const float* BRb = smem + ((uR2 < U)     ? uR2 * TP - uR2      : DUMMY * TP) + FRONT + 1;
        const float* ERb = smem + ((uR2 < U - 1) ? (U + uR2) * TP - uR2: DUMMY * TP) + FRONT;

        const float bfin = smem[ui * TP + FRONT + ti + 1];   // blank[ti][ui]
        float q0 = (u0  == ui) ? bfin : DEAD;                // beta on diag dmax
        float q1 = (u1  == ui) ? bfin : DEAD;
        float qR = (uR2 == ui) ? bfin : DEAD;

        const int d0 = dmax - 1;
        float b0 = B0b[d0], e0 = E0b[d0], b1 = B1b[d0], e1 = E1b[d0], bR = BRb[d0], eR = ERb[d0];
        #pragma unroll 2
        for (int d = d0; d >= D; d--) {
            float nb0 = B0b[d - 1], ne0 = E0b[d - 1];
            float nb1 = B1b[d - 1], ne1 = E1b[d - 1];
            float nbR = BRb[d - 1], neR = ERb[d - 1];

            float sd = __shfl_down_sync(0xffffffff, q1, 1); // lane l+1's col 2l+3

            float nR = la2(qR + bR, sd + eR);   // col 2l+2 (redundant)
            float n1 = la2(q1 + b1, qR + e1);   // col 2l+1
            float n0 = la2(q0 + b0, q1 + e0);   // col 2l

            qR = nR; q1 = n1; q0 = n0;
            b0 = nb0; e0 = ne0; b1 = nb1; e1 = ne1; bR = nbR; eR = neR;
        }
        if (u0 < 64) bbuf[u0] = q0;
        if (u1 < 64) bbuf[u1] = q1;
    }
    __syncthreads();

    // ---------- combine: loss_b = logsumexp_u(alpha_D[u] + beta_D[u]) ----------
    if (wid == 0) {
        int ua = lane, ub = lane + 32;
        float x1 = (ua < U) ? abuf[ua] + bbuf[ua] : DEAD;
        float x2 = (ub < U) ? abuf[ub] + bbuf[ub] : DEAD;
        float m = fmaxf(x1, x2);
        #pragma unroll
        for (int o = 16; o > 0; o >>= 1) m = fmaxf(m, __shfl_xor_sync(0xffffffff, m, o));
        float ea, eb;
        asm("ex2.approx.ftz.f32 %0, %1;" : "=f"(ea) : "f"(x1 - m));
        asm("ex2.approx.ftz.f32 %0, %1;" : "=f"(eb) : "f"(x2 - m));
        float s = ea + eb;
        #pragma unroll
        for (int o = 16; o > 0; o >>= 1) s += __shfl_xor_sync(0xffffffff, s, o);
        if (lane == 0) {
            float l;
            asm("lg2.approx.ftz.f32 %0, %1;" : "=f"(l) : "f"(s));
            g_partial[b] = -(m + l) * LN2;
            __threadfence();
            if (atomicAdd(&g_count, 1u) == B - 1) {
                __threadfence();
                const volatile float* gp = g_partial;
                float acc = 0.0f;
                #pragma unroll
                for (int i = 0; i < B; i++) acc += gp[i];
                out[0] = acc * (1.0f / B);
            }
        }
    }
}

extern "C" void kernel_launch(void* const* d_in, const int* in_sizes, int n_in,
                              void* d_out, int out_size) {
    const float* h           = (const float*)d_in[0];
    const int*   targets     = (const int*)d_in[1];
    const int*   input_lens  = (const int*)d_in[2];
    const int*   target_lens = (const int*)d_in[3];
    float*       out         = (float*)d_out;

    const size_t smem_bytes = ((size_t)NCOLS * TP + 128) * sizeof(float); // 128512 B
    static int smem_set = 0;
    if (!smem_set) {
        cudaFuncSetAttribute(rnnt_dp_kernel,
                             cudaFuncAttributeMaxDynamicSharedMemorySize,
                             (int)smem_bytes);
        smem_set = 1;
    }

    rnnt_gather_kernel<<<(B * NCOL) / 4, 128>>>(h, targets);
    rnnt_dp_kernel<<<B, 512, smem_bytes>>>(input_lens, target_lens, out);
}